// round 4
// baseline (speedup 1.0000x reference)
#include <cuda_runtime.h>
#include <math.h>

// Inputs (metadata order):
//   0: coords     float32 [100000,3]
//   1: pairs      int32   [3200000,2]
//   2: box        float32 [3,3]
//   3: c6         float32 [8,8]
//   4: b          float32 [8,8]
//   5: cutoff     float32 scalar
//   6: atom_types int32   [100000]
// Output: float32 [3200000]
//
// Numerics: the reference f6 = 1 - exp(-u)*poly(u) has catastrophic
// cancellation at small u, amplified by /r^6. The test compares against the
// reference's COMPUTED values, so we must replicate its f32 expression graph
// bitwise: explicit round-to-nearest intrinsics (no FMA contraction, no
// fast-math substitution), exact association order, rn divisions for u/3 etc,
// near-correctly-rounded exp (double exp cast to f32), and an LU/GJ-style box
// inverse matching jnp.linalg.inv.

#define N_TYPES 8

__global__ void dispersion_kernel(
    const float* __restrict__ coords,
    const int2* __restrict__ pairs,
    const float* __restrict__ box,
    const float* __restrict__ c6t,
    const float* __restrict__ bt,
    const float* __restrict__ cutoffp,
    const int* __restrict__ types,
    float* __restrict__ out,
    int n_pairs)
{
    __shared__ float sh_c6[N_TYPES * N_TYPES];
    __shared__ float sh_b[N_TYPES * N_TYPES];
    __shared__ float sh_box[9];
    __shared__ float sh_inv[9];
    __shared__ float sh_cut;

    int tid = threadIdx.x;
    if (tid < N_TYPES * N_TYPES) {
        sh_c6[tid] = c6t[tid];
        sh_b[tid]  = bt[tid];
    }
    if (tid == 0) {
        // Copy box
        float A[3][3], I[3][3];
        #pragma unroll
        for (int r = 0; r < 3; r++)
            #pragma unroll
            for (int c = 0; c < 3; c++) {
                A[r][c] = box[3*r + c];
                I[r][c] = (r == c) ? 1.0f : 0.0f;
                sh_box[3*r + c] = box[3*r + c];
            }
        // Gauss-Jordan with partial pivoting, all ops round-to-nearest f32.
        // For a diagonal box this yields exactly diag(rn(1/L)), matching
        // the LU-based jnp.linalg.inv bitwise.
        #pragma unroll
        for (int col = 0; col < 3; col++) {
            int piv = col;
            float best = fabsf(A[col][col]);
            #pragma unroll
            for (int r = 0; r < 3; r++) {
                if (r > col && fabsf(A[r][col]) > best) {
                    best = fabsf(A[r][col]);
                    piv = r;
                }
            }
            if (piv != col) {
                #pragma unroll
                for (int c = 0; c < 3; c++) {
                    float t = A[col][c]; A[col][c] = A[piv][c]; A[piv][c] = t;
                    t = I[col][c]; I[col][c] = I[piv][c]; I[piv][c] = t;
                }
            }
            float pv = A[col][col];
            #pragma unroll
            for (int c = 0; c < 3; c++) {
                A[col][c] = __fdiv_rn(A[col][c], pv);
                I[col][c] = __fdiv_rn(I[col][c], pv);
            }
            #pragma unroll
            for (int r = 0; r < 3; r++) {
                if (r != col) {
                    float f = A[r][col];
                    #pragma unroll
                    for (int c = 0; c < 3; c++) {
                        A[r][c] = __fsub_rn(A[r][c], __fmul_rn(f, A[col][c]));
                        I[r][c] = __fsub_rn(I[r][c], __fmul_rn(f, I[col][c]));
                    }
                }
            }
        }
        #pragma unroll
        for (int r = 0; r < 3; r++)
            #pragma unroll
            for (int c = 0; c < 3; c++)
                sh_inv[3*r + c] = I[r][c];
        sh_cut = cutoffp[0];
    }
    __syncthreads();

    int i = blockIdx.x * blockDim.x + tid;
    if (i >= n_pairs) return;

    int2 p = __ldg(pairs + i);
    int ia = p.x;
    int ib = p.y;

    float ax = __ldg(coords + 3*ia + 0);
    float ay = __ldg(coords + 3*ia + 1);
    float az = __ldg(coords + 3*ia + 2);
    float bx = __ldg(coords + 3*ib + 0);
    float by = __ldg(coords + 3*ib + 1);
    float bz = __ldg(coords + 3*ib + 2);

    // dr = coords[j] - coords[i]
    float dx = __fsub_rn(bx, ax);
    float dy = __fsub_rn(by, ay);
    float dz = __fsub_rn(bz, az);

    // t = dr @ inv_box  (row vector x matrix), ((a+b)+c) order, no FMA
    float t0 = __fadd_rn(__fadd_rn(__fmul_rn(dx, sh_inv[0]), __fmul_rn(dy, sh_inv[3])), __fmul_rn(dz, sh_inv[6]));
    float t1 = __fadd_rn(__fadd_rn(__fmul_rn(dx, sh_inv[1]), __fmul_rn(dy, sh_inv[4])), __fmul_rn(dz, sh_inv[7]));
    float t2 = __fadd_rn(__fadd_rn(__fmul_rn(dx, sh_inv[2]), __fmul_rn(dy, sh_inv[5])), __fmul_rn(dz, sh_inv[8]));
    // jnp.round = round half to even = rint
    t0 = rintf(t0); t1 = rintf(t1); t2 = rintf(t2);
    // corr = n @ box
    float c0 = __fadd_rn(__fadd_rn(__fmul_rn(t0, sh_box[0]), __fmul_rn(t1, sh_box[3])), __fmul_rn(t2, sh_box[6]));
    float c1 = __fadd_rn(__fadd_rn(__fmul_rn(t0, sh_box[1]), __fmul_rn(t1, sh_box[4])), __fmul_rn(t2, sh_box[7]));
    float c2 = __fadd_rn(__fadd_rn(__fmul_rn(t0, sh_box[2]), __fmul_rn(t1, sh_box[5])), __fmul_rn(t2, sh_box[8]));
    dx = __fsub_rn(dx, c0);
    dy = __fsub_rn(dy, c1);
    dz = __fsub_rn(dz, c2);

    // r = sqrt((dx^2 + dy^2) + dz^2), exact rn
    float r2 = __fadd_rn(__fadd_rn(__fmul_rn(dx, dx), __fmul_rn(dy, dy)), __fmul_rn(dz, dz));
    float r  = __fsqrt_rn(r2);

    if (!(r <= sh_cut)) {
        out[i] = 0.0f;
        return;
    }

    int ti = __ldg(types + ia);
    int tj = __ldg(types + ib);
    float c6ij = sh_c6[ti * N_TYPES + tj];
    float bij  = sh_b [ti * N_TYPES + tj];

    float u = __fmul_rn(bij, r);

    // poly = 1 + u*(1 + u/2*(1 + u/3*(1 + u/4*(1 + u/5*(1 + u/6)))))
    // exact rn divisions and exact association order (replicates reference graph)
    float s = __fadd_rn(1.0f, __fdiv_rn(u, 6.0f));
    s = __fadd_rn(1.0f, __fmul_rn(__fdiv_rn(u, 5.0f), s));
    s = __fadd_rn(1.0f, __fmul_rn(__fdiv_rn(u, 4.0f), s));
    s = __fadd_rn(1.0f, __fmul_rn(__fdiv_rn(u, 3.0f), s));
    s = __fadd_rn(1.0f, __fmul_rn(__fdiv_rn(u, 2.0f), s));
    float poly = __fadd_rn(1.0f, __fmul_rn(u, s));

    // exp(-u): double exp cast to f32 ~ correctly rounded, immune to fast-math
    float g = (float)exp(-(double)u);

    float f6 = __fsub_rn(1.0f, __fmul_rn(g, poly));

    // ene = -(c6*f6)/r^6 ; r^6 rounding is not amplified (relative-only)
    float rr = __fmul_rn(r, r);
    float r6 = __fmul_rn(__fmul_rn(rr, rr), rr);
    out[i] = -__fdiv_rn(__fmul_rn(c6ij, f6), r6);
}

extern "C" void kernel_launch(void* const* d_in, const int* in_sizes, int n_in,
                              void* d_out, int out_size)
{
    const float* coords  = (const float*)d_in[0];
    const int2*  pairs   = (const int2*)d_in[1];
    const float* box     = (const float*)d_in[2];
    const float* c6t     = (const float*)d_in[3];
    const float* bt      = (const float*)d_in[4];
    const float* cutoffp = (const float*)d_in[5];
    const int*   types   = (const int*)d_in[6];
    float*       out     = (float*)d_out;

    int n_pairs = out_size;
    int threads = 256;
    int blocks  = (n_pairs + threads - 1) / threads;
    dispersion_kernel<<<blocks, threads>>>(coords, pairs, box, c6t, bt, cutoffp,
                                           types, out, n_pairs);
}

// round 5
// speedup vs baseline: 1.2383x; 1.2383x over previous
#include <cuda_runtime.h>
#include <math.h>

// Inputs (metadata order):
//   0: coords     float32 [100000,3]
//   1: pairs      int32   [3200000,2]
//   2: box        float32 [3,3]
//   3: c6         float32 [8,8]
//   4: b          float32 [8,8]
//   5: cutoff     float32 scalar
//   6: atom_types int32   [100000]
// Output: float32 [3200000]

#define N_TYPES 8
#define MAX_ATOMS 100000

// Scratch: packed (x, y, z, type-bits) per atom. Static __device__ allocation
// (cudaMalloc is forbidden). 1.6 MB.
__device__ float4 g_atoms[MAX_ATOMS];

__global__ void pack_atoms_kernel(const float* __restrict__ coords,
                                  const int* __restrict__ types,
                                  int n_atoms)
{
    int i = blockIdx.x * blockDim.x + threadIdx.x;
    if (i >= n_atoms) return;
    float4 v;
    v.x = coords[3*i + 0];
    v.y = coords[3*i + 1];
    v.z = coords[3*i + 2];
    v.w = __int_as_float(types[i]);
    g_atoms[i] = v;
}

// ~1-ulp fp32 exp via Cody-Waite reduction + degree-6 minimax (Cephes).
// Valid for x in [-88, 0]; here x = -u, u <= ~21, so j >= -31 -> simple
// exponent-bit scaling is safe. No FP64 anywhere (B200 FP64 pipe is slow).
__device__ __forceinline__ float exp_accurate(float x)
{
    const float LOG2EF = 1.44269504088896341f;
    const float C1 = 0.693359375f;        // ln2_hi (exact in fp32)
    const float C2 = -2.12194440e-4f;     // ln2_lo
    float j = rintf(x * LOG2EF);
    float f = fmaf(-j, C1, x);
    f = fmaf(-j, C2, f);
    float z = f * f;
    float p = 1.9875691500e-4f;
    p = fmaf(p, f, 1.3981999507e-3f);
    p = fmaf(p, f, 8.3334519073e-3f);
    p = fmaf(p, f, 4.1665795894e-2f);
    p = fmaf(p, f, 1.6666665459e-1f);
    p = fmaf(p, f, 5.0000001201e-1f);
    p = fmaf(p, z, f);
    p = p + 1.0f;
    // scale by 2^j
    int e = (int)j;
    float s = __int_as_float((e + 127) << 23);
    return p * s;
}

__global__ void dispersion_kernel(
    const int2* __restrict__ pairs,
    const float* __restrict__ box,
    const float* __restrict__ c6t,
    const float* __restrict__ bt,
    const float* __restrict__ cutoffp,
    float* __restrict__ out,
    int n_pairs)
{
    __shared__ float sh_c6[N_TYPES * N_TYPES];
    __shared__ float sh_b[N_TYPES * N_TYPES];
    __shared__ float sh_box[9];
    __shared__ float sh_inv[9];
    __shared__ float sh_cut;

    int tid = threadIdx.x;
    if (tid < N_TYPES * N_TYPES) {
        sh_c6[tid] = c6t[tid];
        sh_b[tid]  = bt[tid];
    }
    if (tid == 0) {
        // Gauss-Jordan with partial pivoting, all ops rn-f32 (matches
        // LU-based jnp.linalg.inv bitwise for well-behaved boxes).
        float A[3][3], I[3][3];
        #pragma unroll
        for (int r = 0; r < 3; r++)
            #pragma unroll
            for (int c = 0; c < 3; c++) {
                A[r][c] = box[3*r + c];
                I[r][c] = (r == c) ? 1.0f : 0.0f;
                sh_box[3*r + c] = box[3*r + c];
            }
        #pragma unroll
        for (int col = 0; col < 3; col++) {
            int piv = col;
            float best = fabsf(A[col][col]);
            #pragma unroll
            for (int r = 0; r < 3; r++) {
                if (r > col && fabsf(A[r][col]) > best) {
                    best = fabsf(A[r][col]);
                    piv = r;
                }
            }
            if (piv != col) {
                #pragma unroll
                for (int c = 0; c < 3; c++) {
                    float t = A[col][c]; A[col][c] = A[piv][c]; A[piv][c] = t;
                    t = I[col][c]; I[col][c] = I[piv][c]; I[piv][c] = t;
                }
            }
            float pv = A[col][col];
            #pragma unroll
            for (int c = 0; c < 3; c++) {
                A[col][c] = __fdiv_rn(A[col][c], pv);
                I[col][c] = __fdiv_rn(I[col][c], pv);
            }
            #pragma unroll
            for (int r = 0; r < 3; r++) {
                if (r != col) {
                    float fr = A[r][col];
                    #pragma unroll
                    for (int c = 0; c < 3; c++) {
                        A[r][c] = __fsub_rn(A[r][c], __fmul_rn(fr, A[col][c]));
                        I[r][c] = __fsub_rn(I[r][c], __fmul_rn(fr, I[col][c]));
                    }
                }
            }
        }
        #pragma unroll
        for (int r = 0; r < 3; r++)
            #pragma unroll
            for (int c = 0; c < 3; c++)
                sh_inv[3*r + c] = I[r][c];
        sh_cut = cutoffp[0];
    }
    __syncthreads();

    int i = blockIdx.x * blockDim.x + tid;
    if (i >= n_pairs) return;

    int2 p = __ldg(pairs + i);

    // Two aligned 16B gathers (coords + type packed)
    float4 a = __ldg(&g_atoms[p.x]);
    float4 bAtom = __ldg(&g_atoms[p.y]);

    // dr = coords[j] - coords[i], exact rn chain (replicates reference graph)
    float dx = __fsub_rn(bAtom.x, a.x);
    float dy = __fsub_rn(bAtom.y, a.y);
    float dz = __fsub_rn(bAtom.z, a.z);

    // t = dr @ inv_box, ((a+b)+c) order, no FMA
    float t0 = __fadd_rn(__fadd_rn(__fmul_rn(dx, sh_inv[0]), __fmul_rn(dy, sh_inv[3])), __fmul_rn(dz, sh_inv[6]));
    float t1 = __fadd_rn(__fadd_rn(__fmul_rn(dx, sh_inv[1]), __fmul_rn(dy, sh_inv[4])), __fmul_rn(dz, sh_inv[7]));
    float t2 = __fadd_rn(__fadd_rn(__fmul_rn(dx, sh_inv[2]), __fmul_rn(dy, sh_inv[5])), __fmul_rn(dz, sh_inv[8]));
    t0 = rintf(t0); t1 = rintf(t1); t2 = rintf(t2);
    float c0 = __fadd_rn(__fadd_rn(__fmul_rn(t0, sh_box[0]), __fmul_rn(t1, sh_box[3])), __fmul_rn(t2, sh_box[6]));
    float c1 = __fadd_rn(__fadd_rn(__fmul_rn(t0, sh_box[1]), __fmul_rn(t1, sh_box[4])), __fmul_rn(t2, sh_box[7]));
    float c2 = __fadd_rn(__fadd_rn(__fmul_rn(t0, sh_box[2]), __fmul_rn(t1, sh_box[5])), __fmul_rn(t2, sh_box[8]));
    dx = __fsub_rn(dx, c0);
    dy = __fsub_rn(dy, c1);
    dz = __fsub_rn(dz, c2);

    float r2 = __fadd_rn(__fadd_rn(__fmul_rn(dx, dx), __fmul_rn(dy, dy)), __fmul_rn(dz, dz));
    float r  = __fsqrt_rn(r2);

    if (!(r <= sh_cut)) {
        out[i] = 0.0f;
        return;
    }

    int ti = __float_as_int(a.w);
    int tj = __float_as_int(bAtom.w);
    float c6ij = sh_c6[ti * N_TYPES + tj];
    float bij  = sh_b [ti * N_TYPES + tj];

    float u = __fmul_rn(bij, r);

    // poly = 1 + u*(1 + u/2*(1 + u/3*(1 + u/4*(1 + u/5*(1 + u/6)))))
    float s = __fadd_rn(1.0f, __fdiv_rn(u, 6.0f));
    s = __fadd_rn(1.0f, __fmul_rn(__fdiv_rn(u, 5.0f), s));
    s = __fadd_rn(1.0f, __fmul_rn(__fdiv_rn(u, 4.0f), s));
    s = __fadd_rn(1.0f, __fmul_rn(__fdiv_rn(u, 3.0f), s));
    s = __fadd_rn(1.0f, __fmul_rn(__fdiv_rn(u, 2.0f), s));
    float poly = __fadd_rn(1.0f, __fmul_rn(u, s));

    float g = exp_accurate(-u);
    float f6 = __fsub_rn(1.0f, __fmul_rn(g, poly));

    float rr = __fmul_rn(r, r);
    float r6 = __fmul_rn(__fmul_rn(rr, rr), rr);
    out[i] = -__fdiv_rn(__fmul_rn(c6ij, f6), r6);
}

extern "C" void kernel_launch(void* const* d_in, const int* in_sizes, int n_in,
                              void* d_out, int out_size)
{
    const float* coords  = (const float*)d_in[0];
    const int2*  pairs   = (const int2*)d_in[1];
    const float* box     = (const float*)d_in[2];
    const float* c6t     = (const float*)d_in[3];
    const float* bt      = (const float*)d_in[4];
    const float* cutoffp = (const float*)d_in[5];
    const int*   types   = (const int*)d_in[6];
    float*       out     = (float*)d_out;

    int n_atoms = in_sizes[0] / 3;
    int n_pairs = out_size;

    pack_atoms_kernel<<<(n_atoms + 255) / 256, 256>>>(coords, types, n_atoms);

    int threads = 256;
    int blocks  = (n_pairs + threads - 1) / threads;
    dispersion_kernel<<<blocks, threads>>>(pairs, box, c6t, bt, cutoffp,
                                           out, n_pairs);
}

// round 6
// speedup vs baseline: 1.3373x; 1.0800x over previous
#include <cuda_runtime.h>
#include <math.h>

// Inputs (metadata order):
//   0: coords     float32 [100000,3]
//   1: pairs      int32   [3200000,2]
//   2: box        float32 [3,3]
//   3: c6         float32 [8,8]
//   4: b          float32 [8,8]
//   5: cutoff     float32 scalar
//   6: atom_types int32   [100000]
// Output: float32 [3200000]

#define N_TYPES 8
#define MAX_ATOMS 100000

__device__ float4 g_atoms[MAX_ATOMS];

__global__ void pack_atoms_kernel(const float* __restrict__ coords,
                                  const int* __restrict__ types,
                                  int n_atoms)
{
    int i = blockIdx.x * blockDim.x + threadIdx.x;
    if (i >= n_atoms) return;
    float4 v;
    v.x = coords[3*i + 0];
    v.y = coords[3*i + 1];
    v.z = coords[3*i + 2];
    v.w = __int_as_float(types[i]);
    g_atoms[i] = v;
}

// ~1-ulp fp32 exp (Cody-Waite + degree-6 minimax). x in [-88, 0].
__device__ __forceinline__ float exp_accurate(float x)
{
    const float LOG2EF = 1.44269504088896341f;
    const float C1 = 0.693359375f;
    const float C2 = -2.12194440e-4f;
    float j = rintf(x * LOG2EF);
    float f = fmaf(-j, C1, x);
    f = fmaf(-j, C2, f);
    float z = f * f;
    float p = 1.9875691500e-4f;
    p = fmaf(p, f, 1.3981999507e-3f);
    p = fmaf(p, f, 8.3334519073e-3f);
    p = fmaf(p, f, 4.1665795894e-2f);
    p = fmaf(p, f, 1.6666665459e-1f);
    p = fmaf(p, f, 5.0000001201e-1f);
    p = fmaf(p, z, f);
    p = p + 1.0f;
    int e = (int)j;
    float s = __int_as_float((e + 127) << 23);
    return p * s;
}

struct BoxCtx {
    float box[9];
    float inv[9];
    float cut;
    int   diag;   // 1 if box and inv are strictly diagonal
};

// Per-pair energy, replicating the reference f32 expression graph bitwise.
__device__ __forceinline__ float pair_energy(
    const float4 a, const float4 b,
    const float* __restrict__ sh_box, const float* __restrict__ sh_inv,
    float cut, int diag,
    const float* __restrict__ sh_c6, const float* __restrict__ sh_b)
{
    float dx = __fsub_rn(b.x, a.x);
    float dy = __fsub_rn(b.y, a.y);
    float dz = __fsub_rn(b.z, a.z);

    if (diag) {
        // Bitwise-equal to the full chain when all off-diagonals are +0:
        // rn(rn(dx*inv00) + 0 + 0) == rn(dx*inv00); squares kill +-0 signs.
        float t0 = rintf(__fmul_rn(dx, sh_inv[0]));
        float t1 = rintf(__fmul_rn(dy, sh_inv[4]));
        float t2 = rintf(__fmul_rn(dz, sh_inv[8]));
        dx = __fsub_rn(dx, __fmul_rn(t0, sh_box[0]));
        dy = __fsub_rn(dy, __fmul_rn(t1, sh_box[4]));
        dz = __fsub_rn(dz, __fmul_rn(t2, sh_box[8]));
    } else {
        float t0 = __fadd_rn(__fadd_rn(__fmul_rn(dx, sh_inv[0]), __fmul_rn(dy, sh_inv[3])), __fmul_rn(dz, sh_inv[6]));
        float t1 = __fadd_rn(__fadd_rn(__fmul_rn(dx, sh_inv[1]), __fmul_rn(dy, sh_inv[4])), __fmul_rn(dz, sh_inv[7]));
        float t2 = __fadd_rn(__fadd_rn(__fmul_rn(dx, sh_inv[2]), __fmul_rn(dy, sh_inv[5])), __fmul_rn(dz, sh_inv[8]));
        t0 = rintf(t0); t1 = rintf(t1); t2 = rintf(t2);
        float c0 = __fadd_rn(__fadd_rn(__fmul_rn(t0, sh_box[0]), __fmul_rn(t1, sh_box[3])), __fmul_rn(t2, sh_box[6]));
        float c1 = __fadd_rn(__fadd_rn(__fmul_rn(t0, sh_box[1]), __fmul_rn(t1, sh_box[4])), __fmul_rn(t2, sh_box[7]));
        float c2 = __fadd_rn(__fadd_rn(__fmul_rn(t0, sh_box[2]), __fmul_rn(t1, sh_box[5])), __fmul_rn(t2, sh_box[8]));
        dx = __fsub_rn(dx, c0);
        dy = __fsub_rn(dy, c1);
        dz = __fsub_rn(dz, c2);
    }

    float r2 = __fadd_rn(__fadd_rn(__fmul_rn(dx, dx), __fmul_rn(dy, dy)), __fmul_rn(dz, dz));
    float r  = __fsqrt_rn(r2);

    if (!(r <= cut)) return 0.0f;

    int ti = __float_as_int(a.w);
    int tj = __float_as_int(b.w);
    float c6ij = sh_c6[ti * N_TYPES + tj];
    float bij  = sh_b [ti * N_TYPES + tj];

    float u = __fmul_rn(bij, r);

    // poly = 1 + u*(1 + u/2*(1 + u/3*(1 + u/4*(1 + u/5*(1 + u/6)))))
    // u/2, u/4 as exact power-of-two multiplies (bitwise identical to division)
    float s = __fadd_rn(1.0f, __fdiv_rn(u, 6.0f));
    s = __fadd_rn(1.0f, __fmul_rn(__fdiv_rn(u, 5.0f), s));
    s = __fadd_rn(1.0f, __fmul_rn(__fmul_rn(u, 0.25f), s));
    s = __fadd_rn(1.0f, __fmul_rn(__fdiv_rn(u, 3.0f), s));
    s = __fadd_rn(1.0f, __fmul_rn(__fmul_rn(u, 0.5f), s));
    float poly = __fadd_rn(1.0f, __fmul_rn(u, s));

    float g = exp_accurate(-u);
    float f6 = __fsub_rn(1.0f, __fmul_rn(g, poly));

    float rr = __fmul_rn(r, r);
    float r6 = __fmul_rn(__fmul_rn(rr, rr), rr);
    return -__fdiv_rn(__fmul_rn(c6ij, f6), r6);
}

__global__ void dispersion_kernel(
    const int4* __restrict__ pairs2,   // 2 pairs per element
    const float* __restrict__ box,
    const float* __restrict__ c6t,
    const float* __restrict__ bt,
    const float* __restrict__ cutoffp,
    float2* __restrict__ out2,
    int n_half)                        // n_pairs / 2
{
    __shared__ float sh_c6[N_TYPES * N_TYPES];
    __shared__ float sh_b[N_TYPES * N_TYPES];
    __shared__ BoxCtx sh_ctx;

    int tid = threadIdx.x;
    if (tid < N_TYPES * N_TYPES) {
        sh_c6[tid] = c6t[tid];
        sh_b[tid]  = bt[tid];
    }
    if (tid == 0) {
        float A[3][3], I[3][3];
        #pragma unroll
        for (int r = 0; r < 3; r++)
            #pragma unroll
            for (int c = 0; c < 3; c++) {
                A[r][c] = box[3*r + c];
                I[r][c] = (r == c) ? 1.0f : 0.0f;
                sh_ctx.box[3*r + c] = box[3*r + c];
            }
        // Gauss-Jordan with partial pivoting, rn-f32 (matches jnp.linalg.inv)
        #pragma unroll
        for (int col = 0; col < 3; col++) {
            int piv = col;
            float best = fabsf(A[col][col]);
            #pragma unroll
            for (int r = 0; r < 3; r++)
                if (r > col && fabsf(A[r][col]) > best) { best = fabsf(A[r][col]); piv = r; }
            if (piv != col) {
                #pragma unroll
                for (int c = 0; c < 3; c++) {
                    float t = A[col][c]; A[col][c] = A[piv][c]; A[piv][c] = t;
                    t = I[col][c]; I[col][c] = I[piv][c]; I[piv][c] = t;
                }
            }
            float pv = A[col][col];
            #pragma unroll
            for (int c = 0; c < 3; c++) {
                A[col][c] = __fdiv_rn(A[col][c], pv);
                I[col][c] = __fdiv_rn(I[col][c], pv);
            }
            #pragma unroll
            for (int r = 0; r < 3; r++)
                if (r != col) {
                    float fr = A[r][col];
                    #pragma unroll
                    for (int c = 0; c < 3; c++) {
                        A[r][c] = __fsub_rn(A[r][c], __fmul_rn(fr, A[col][c]));
                        I[r][c] = __fsub_rn(I[r][c], __fmul_rn(fr, I[col][c]));
                    }
                }
        }
        int diag = 1;
        #pragma unroll
        for (int r = 0; r < 3; r++)
            #pragma unroll
            for (int c = 0; c < 3; c++) {
                sh_ctx.inv[3*r + c] = I[r][c];
                if (r != c && (I[r][c] != 0.0f || sh_ctx.box[3*r + c] != 0.0f)) diag = 0;
            }
        sh_ctx.diag = diag;
        sh_ctx.cut  = cutoffp[0];
    }
    __syncthreads();

    int idx = blockIdx.x * blockDim.x + tid;
    if (idx >= n_half) return;

    int4 pp = __ldg(pairs2 + idx);

    // Issue all four gathers up front (MLP = 4)
    float4 a0 = __ldg(&g_atoms[pp.x]);
    float4 b0 = __ldg(&g_atoms[pp.y]);
    float4 a1 = __ldg(&g_atoms[pp.z]);
    float4 b1 = __ldg(&g_atoms[pp.w]);

    float cut = sh_ctx.cut;
    int diag  = sh_ctx.diag;

    float e0 = pair_energy(a0, b0, sh_ctx.box, sh_ctx.inv, cut, diag, sh_c6, sh_b);
    float e1 = pair_energy(a1, b1, sh_ctx.box, sh_ctx.inv, cut, diag, sh_c6, sh_b);

    out2[idx] = make_float2(e0, e1);
}

// Scalar fallback for a possible odd tail pair
__global__ void dispersion_tail_kernel(
    const int2* __restrict__ pairs,
    const float* __restrict__ box,
    const float* __restrict__ c6t,
    const float* __restrict__ bt,
    const float* __restrict__ cutoffp,
    float* __restrict__ out,
    int start, int n_pairs)
{
    int i = start + blockIdx.x * blockDim.x + threadIdx.x;
    if (i >= n_pairs) return;
    // (small: reuse general path without shared staging)
    float inv[9], B[9];
    // adjugate fallback is fine here only if never used for real data; to stay
    // safe, recompute GJ inverse per thread (tail is at most 1 element).
    float A[3][3], I[3][3];
    for (int r = 0; r < 3; r++)
        for (int c = 0; c < 3; c++) {
            A[r][c] = box[3*r + c];
            I[r][c] = (r == c) ? 1.0f : 0.0f;
            B[3*r + c] = box[3*r + c];
        }
    for (int col = 0; col < 3; col++) {
        int piv = col;
        float best = fabsf(A[col][col]);
        for (int r = col + 1; r < 3; r++)
            if (fabsf(A[r][col]) > best) { best = fabsf(A[r][col]); piv = r; }
        if (piv != col)
            for (int c = 0; c < 3; c++) {
                float t = A[col][c]; A[col][c] = A[piv][c]; A[piv][c] = t;
                t = I[col][c]; I[col][c] = I[piv][c]; I[piv][c] = t;
            }
        float pv = A[col][col];
        for (int c = 0; c < 3; c++) {
            A[col][c] = __fdiv_rn(A[col][c], pv);
            I[col][c] = __fdiv_rn(I[col][c], pv);
        }
        for (int r = 0; r < 3; r++)
            if (r != col) {
                float fr = A[r][col];
                for (int c = 0; c < 3; c++) {
                    A[r][c] = __fsub_rn(A[r][c], __fmul_rn(fr, A[col][c]));
                    I[r][c] = __fsub_rn(I[r][c], __fmul_rn(fr, I[col][c]));
                }
            }
    }
    for (int r = 0; r < 3; r++)
        for (int c = 0; c < 3; c++) inv[3*r + c] = I[r][c];

    int2 p = __ldg(pairs + i);
    float4 a = __ldg(&g_atoms[p.x]);
    float4 bb = __ldg(&g_atoms[p.y]);
    // reuse math via local tables
    float c6loc[64], bloc[64];
    for (int k = 0; k < 64; k++) { c6loc[k] = c6t[k]; bloc[k] = bt[k]; }
    out[i] = pair_energy(a, bb, B, inv, cutoffp[0], 0, c6loc, bloc);
}

extern "C" void kernel_launch(void* const* d_in, const int* in_sizes, int n_in,
                              void* d_out, int out_size)
{
    const float* coords  = (const float*)d_in[0];
    const int4*  pairs2  = (const int4*)d_in[1];
    const float* box     = (const float*)d_in[2];
    const float* c6t     = (const float*)d_in[3];
    const float* bt      = (const float*)d_in[4];
    const float* cutoffp = (const float*)d_in[5];
    const int*   types   = (const int*)d_in[6];
    float*       out     = (float*)d_out;

    int n_atoms = in_sizes[0] / 3;
    int n_pairs = out_size;
    int n_half  = n_pairs / 2;

    pack_atoms_kernel<<<(n_atoms + 255) / 256, 256>>>(coords, types, n_atoms);

    int threads = 256;
    int blocks  = (n_half + threads - 1) / threads;
    dispersion_kernel<<<blocks, threads>>>(pairs2, box, c6t, bt, cutoffp,
                                           (float2*)out, n_half);
    if (n_pairs & 1) {
        dispersion_tail_kernel<<<1, 32>>>((const int2*)d_in[1], box, c6t, bt,
                                          cutoffp, out, n_half * 2, n_pairs);
    }
}

// round 8
// speedup vs baseline: 1.5141x; 1.1322x over previous
#include <cuda_runtime.h>
#include <math.h>

// Inputs (metadata order):
//   0: coords     float32 [100000,3]
//   1: pairs      int32   [3200000,2]
//   2: box        float32 [3,3]
//   3: c6         float32 [8,8]
//   4: b          float32 [8,8]
//   5: cutoff     float32 scalar
//   6: atom_types int32   [100000]
// Output: float32 [3200000]

#define N_TYPES 8
#define MAX_ATOMS 100000

__device__ float4 g_atoms[MAX_ATOMS];

__global__ void pack_atoms_kernel(const float* __restrict__ coords,
                                  const int* __restrict__ types,
                                  int n_atoms)
{
    int i = blockIdx.x * blockDim.x + threadIdx.x;
    if (i >= n_atoms) return;
    float4 v;
    v.x = coords[3*i + 0];
    v.y = coords[3*i + 1];
    v.z = coords[3*i + 2];
    v.w = __int_as_float(types[i]);
    g_atoms[i] = v;
}

// ~1-ulp fp32 exp (Cody-Waite + degree-6 minimax). x in [-88, 0].
__device__ __forceinline__ float exp_accurate(float x)
{
    const float LOG2EF = 1.44269504088896341f;
    const float C1 = 0.693359375f;
    const float C2 = -2.12194440e-4f;
    float j = rintf(x * LOG2EF);
    float f = fmaf(-j, C1, x);
    f = fmaf(-j, C2, f);
    float z = f * f;
    float p = 1.9875691500e-4f;
    p = fmaf(p, f, 1.3981999507e-3f);
    p = fmaf(p, f, 8.3334519073e-3f);
    p = fmaf(p, f, 4.1665795894e-2f);
    p = fmaf(p, f, 1.6666665459e-1f);
    p = fmaf(p, f, 5.0000001201e-1f);
    p = fmaf(p, z, f);
    p = p + 1.0f;
    int e = (int)j;
    float s = __int_as_float((e + 127) << 23);
    return p * s;
}

// Per-pair energy, replicating the reference f32 expression graph bitwise.
__device__ __forceinline__ float pair_energy(
    const float4 a, const float4 b,
    const float* __restrict__ sh_box, const float* __restrict__ sh_inv,
    float cut, int diag,
    const float* __restrict__ sh_c6, const float* __restrict__ sh_b)
{
    float dx = __fsub_rn(b.x, a.x);
    float dy = __fsub_rn(b.y, a.y);
    float dz = __fsub_rn(b.z, a.z);

    if (diag) {
        // Bitwise-equal to full chain when off-diagonals are +0.
        float t0 = rintf(__fmul_rn(dx, sh_inv[0]));
        float t1 = rintf(__fmul_rn(dy, sh_inv[4]));
        float t2 = rintf(__fmul_rn(dz, sh_inv[8]));
        dx = __fsub_rn(dx, __fmul_rn(t0, sh_box[0]));
        dy = __fsub_rn(dy, __fmul_rn(t1, sh_box[4]));
        dz = __fsub_rn(dz, __fmul_rn(t2, sh_box[8]));
    } else {
        float t0 = __fadd_rn(__fadd_rn(__fmul_rn(dx, sh_inv[0]), __fmul_rn(dy, sh_inv[3])), __fmul_rn(dz, sh_inv[6]));
        float t1 = __fadd_rn(__fadd_rn(__fmul_rn(dx, sh_inv[1]), __fmul_rn(dy, sh_inv[4])), __fmul_rn(dz, sh_inv[7]));
        float t2 = __fadd_rn(__fadd_rn(__fmul_rn(dx, sh_inv[2]), __fmul_rn(dy, sh_inv[5])), __fmul_rn(dz, sh_inv[8]));
        t0 = rintf(t0); t1 = rintf(t1); t2 = rintf(t2);
        float c0 = __fadd_rn(__fadd_rn(__fmul_rn(t0, sh_box[0]), __fmul_rn(t1, sh_box[3])), __fmul_rn(t2, sh_box[6]));
        float c1 = __fadd_rn(__fadd_rn(__fmul_rn(t0, sh_box[1]), __fmul_rn(t1, sh_box[4])), __fmul_rn(t2, sh_box[7]));
        float c2 = __fadd_rn(__fadd_rn(__fmul_rn(t0, sh_box[2]), __fmul_rn(t1, sh_box[5])), __fmul_rn(t2, sh_box[8]));
        dx = __fsub_rn(dx, c0);
        dy = __fsub_rn(dy, c1);
        dz = __fsub_rn(dz, c2);
    }

    float r2 = __fadd_rn(__fadd_rn(__fmul_rn(dx, dx), __fmul_rn(dy, dy)), __fmul_rn(dz, dz));
    float r  = __fsqrt_rn(r2);

    if (!(r <= cut)) return 0.0f;

    int ti = __float_as_int(a.w);
    int tj = __float_as_int(b.w);
    float c6ij = sh_c6[ti * N_TYPES + tj];
    float bij  = sh_b [ti * N_TYPES + tj];

    float u = __fmul_rn(bij, r);

    // poly = 1 + u*(1 + u/2*(1 + u/3*(1 + u/4*(1 + u/5*(1 + u/6)))))
    float s = __fadd_rn(1.0f, __fdiv_rn(u, 6.0f));
    s = __fadd_rn(1.0f, __fmul_rn(__fdiv_rn(u, 5.0f), s));
    s = __fadd_rn(1.0f, __fmul_rn(__fmul_rn(u, 0.25f), s));
    s = __fadd_rn(1.0f, __fmul_rn(__fdiv_rn(u, 3.0f), s));
    s = __fadd_rn(1.0f, __fmul_rn(__fmul_rn(u, 0.5f), s));
    float poly = __fadd_rn(1.0f, __fmul_rn(u, s));

    float g = exp_accurate(-u);
    float f6 = __fsub_rn(1.0f, __fmul_rn(g, poly));

    float rr = __fmul_rn(r, r);
    float r6 = __fmul_rn(__fmul_rn(rr, rr), rr);
    return -__fdiv_rn(__fmul_rn(c6ij, f6), r6);
}

// Shared one-time setup: tables + GJ box inverse + diag detection.
__device__ __forceinline__ void setup_shared(
    float* sh_c6, float* sh_b, float* sh_box, float* sh_inv,
    float* sh_cut, int* sh_diag,
    const float* c6t, const float* bt, const float* box, const float* cutoffp,
    int tid)
{
    if (tid < N_TYPES * N_TYPES) {
        sh_c6[tid] = c6t[tid];
        sh_b[tid]  = bt[tid];
    }
    if (tid == 0) {
        float A[3][3], I[3][3];
        #pragma unroll
        for (int r = 0; r < 3; r++)
            #pragma unroll
            for (int c = 0; c < 3; c++) {
                A[r][c] = box[3*r + c];
                I[r][c] = (r == c) ? 1.0f : 0.0f;
                sh_box[3*r + c] = box[3*r + c];
            }
        #pragma unroll
        for (int col = 0; col < 3; col++) {
            int piv = col;
            float best = fabsf(A[col][col]);
            #pragma unroll
            for (int r = 0; r < 3; r++)
                if (r > col && fabsf(A[r][col]) > best) { best = fabsf(A[r][col]); piv = r; }
            if (piv != col) {
                #pragma unroll
                for (int c = 0; c < 3; c++) {
                    float t = A[col][c]; A[col][c] = A[piv][c]; A[piv][c] = t;
                    t = I[col][c]; I[col][c] = I[piv][c]; I[piv][c] = t;
                }
            }
            float pv = A[col][col];
            #pragma unroll
            for (int c = 0; c < 3; c++) {
                A[col][c] = __fdiv_rn(A[col][c], pv);
                I[col][c] = __fdiv_rn(I[col][c], pv);
            }
            #pragma unroll
            for (int r = 0; r < 3; r++)
                if (r != col) {
                    float fr = A[r][col];
                    #pragma unroll
                    for (int c = 0; c < 3; c++) {
                        A[r][c] = __fsub_rn(A[r][c], __fmul_rn(fr, A[col][c]));
                        I[r][c] = __fsub_rn(I[r][c], __fmul_rn(fr, I[col][c]));
                    }
                }
        }
        int diag = 1;
        #pragma unroll
        for (int r = 0; r < 3; r++)
            #pragma unroll
            for (int c = 0; c < 3; c++) {
                sh_inv[3*r + c] = I[r][c];
                if (r != c && (I[r][c] != 0.0f || sh_box[3*r + c] != 0.0f)) diag = 0;
            }
        *sh_diag = diag;
        *sh_cut  = cutoffp[0];
    }
}

__global__ __launch_bounds__(256, 4)
void dispersion_kernel4(
    const int4* __restrict__ pairs2,   // 2 pairs per int4
    const float* __restrict__ box,
    const float* __restrict__ c6t,
    const float* __restrict__ bt,
    const float* __restrict__ cutoffp,
    float4* __restrict__ out4,
    int n_quarter)                     // n_pairs / 4
{
    __shared__ float sh_c6[N_TYPES * N_TYPES];
    __shared__ float sh_b[N_TYPES * N_TYPES];
    __shared__ float sh_box[9];
    __shared__ float sh_inv[9];
    __shared__ float sh_cut;
    __shared__ int   sh_diag;

    int tid = threadIdx.x;
    setup_shared(sh_c6, sh_b, sh_box, sh_inv, &sh_cut, &sh_diag,
                 c6t, bt, box, cutoffp, tid);
    __syncthreads();

    int idx = blockIdx.x * blockDim.x + tid;
    if (idx >= n_quarter) return;

    int4 pA = __ldg(pairs2 + 2*idx + 0);
    int4 pB = __ldg(pairs2 + 2*idx + 1);

    // Issue all eight gathers up front (MLP = 8)
    float4 a0 = __ldg(&g_atoms[pA.x]);
    float4 b0 = __ldg(&g_atoms[pA.y]);
    float4 a1 = __ldg(&g_atoms[pA.z]);
    float4 b1 = __ldg(&g_atoms[pA.w]);
    float4 a2 = __ldg(&g_atoms[pB.x]);
    float4 b2 = __ldg(&g_atoms[pB.y]);
    float4 a3 = __ldg(&g_atoms[pB.z]);
    float4 b3 = __ldg(&g_atoms[pB.w]);

    float cut = sh_cut;
    int diag  = sh_diag;

    float4 e;
    e.x = pair_energy(a0, b0, sh_box, sh_inv, cut, diag, sh_c6, sh_b);
    e.y = pair_energy(a1, b1, sh_box, sh_inv, cut, diag, sh_c6, sh_b);
    e.z = pair_energy(a2, b2, sh_box, sh_inv, cut, diag, sh_c6, sh_b);
    e.w = pair_energy(a3, b3, sh_box, sh_inv, cut, diag, sh_c6, sh_b);

    out4[idx] = e;
}

// Scalar tail for n_pairs % 4 leftover pairs (not hit for 3.2M).
__global__ void dispersion_tail_kernel(
    const int2* __restrict__ pairs,
    const float* __restrict__ box,
    const float* __restrict__ c6t,
    const float* __restrict__ bt,
    const float* __restrict__ cutoffp,
    float* __restrict__ out,
    int start, int n_pairs)
{
    __shared__ float sh_c6[N_TYPES * N_TYPES];
    __shared__ float sh_b[N_TYPES * N_TYPES];
    __shared__ float sh_box[9];
    __shared__ float sh_inv[9];
    __shared__ float sh_cut;
    __shared__ int   sh_diag;

    int tid = threadIdx.x;
    setup_shared(sh_c6, sh_b, sh_box, sh_inv, &sh_cut, &sh_diag,
                 c6t, bt, box, cutoffp, tid);
    __syncthreads();

    int i = start + blockIdx.x * blockDim.x + tid;
    if (i >= n_pairs) return;

    int2 p = __ldg(pairs + i);
    float4 a = __ldg(&g_atoms[p.x]);
    float4 b = __ldg(&g_atoms[p.y]);
    out[i] = pair_energy(a, b, sh_box, sh_inv, sh_cut, sh_diag, sh_c6, sh_b);
}

extern "C" void kernel_launch(void* const* d_in, const int* in_sizes, int n_in,
                              void* d_out, int out_size)
{
    const float* coords  = (const float*)d_in[0];
    const int4*  pairs2  = (const int4*)d_in[1];
    const float* box     = (const float*)d_in[2];
    const float* c6t     = (const float*)d_in[3];
    const float* bt      = (const float*)d_in[4];
    const float* cutoffp = (const float*)d_in[5];
    const int*   types   = (const int*)d_in[6];
    float*       out     = (float*)d_out;

    int n_atoms   = in_sizes[0] / 3;
    int n_pairs   = out_size;
    int n_quarter = n_pairs / 4;

    pack_atoms_kernel<<<(n_atoms + 255) / 256, 256>>>(coords, types, n_atoms);

    int threads = 256;
    int blocks  = (n_quarter + threads - 1) / threads;
    dispersion_kernel4<<<blocks, threads>>>(pairs2, box, c6t, bt, cutoffp,
                                            (float4*)out, n_quarter);
    if (n_pairs & 3) {
        dispersion_tail_kernel<<<1, 32>>>((const int2*)d_in[1], box, c6t, bt,
                                          cutoffp, out, n_quarter * 4, n_pairs);
    }
}